// round 13
// baseline (speedup 1.0000x reference)
#include <cuda_runtime.h>
#include <stdint.h>
#include <math.h>

#define VSZ 32000
#define ESZ 400
#define HSZ 1150
#define HPAD 1152
#define BSZ 16
#define TSZ 128
#define GP12 4608
#define GP3  1600
#define FLAGSTRIDE 32
#define NSL 16

// GEMM tiling: BM=BN=128, BK=16, interleaved (hi,lo) pairs -> 40 floats/row
#define ASTRIDE 40
#define GEMM_SMEM (2 * 2 * 128 * ASTRIDE * 4)   // 81920 B (A+B, double-buffered)

// ---------------- scratch ----------------
__device__ float g_y0s[TSZ*BSZ*ESZ*2];
__device__ float g_y1s[TSZ*BSZ*HPAD*2];
__device__ float g_y2s[TSZ*BSZ*HPAD*2];
__device__ float g_y3s[TSZ*BSZ*ESZ*2];
__device__ float g_pre[TSZ*BSZ*4*HSZ];
__device__ float g_Wt1[HSZ*GP12];
__device__ float g_Wt2[HSZ*GP12];
__device__ float g_Wt3[ESZ*GP3];
__device__ float g_W1s[4*HSZ*ESZ*2];
__device__ float g_W2s[4*HSZ*HPAD*2];
__device__ float g_W3s[4*ESZ*HPAD*2];
__device__ float g_embs[VSZ*ESZ*2];
__device__ float g_hTa[HSZ*BSZ];
__device__ float g_hTb[HSZ*BSZ];
__device__ float g_cT1[HSZ*BSZ];
__device__ float g_cT2[HSZ*BSZ];
__device__ float g_cT3[ESZ*BSZ];
__device__ unsigned g_flags[3 * 144 * FLAGSTRIDE];

// ---------------- tf32 helpers ----------------
__device__ __forceinline__ float tf32_rna(float x) {
    float r;
    asm("cvt.rna.tf32.f32 %0, %1;" : "=f"(r) : "f"(x));
    return r;
}

// ---------------- prep kernels ----------------
__global__ void split_k(const float* __restrict__ src, float* __restrict__ dst, int n) {
    int i = blockIdx.x * blockDim.x + threadIdx.x;
    if (i >= n) return;
    float v = src[i];
    float hi = tf32_rna(v);
    *(float2*)&dst[(size_t)i * 2] = make_float2(hi, tf32_rna(v - hi));
}

__global__ void padsplit_k(const float* __restrict__ src, float* __restrict__ dst,
                           int rows, int Kin, int Kout) {
    int idx = blockIdx.x * blockDim.x + threadIdx.x;
    if (idx >= rows * Kout) return;
    int r = idx / Kout, k = idx % Kout;
    float v = (k < Kin) ? src[(size_t)r * Kin + k] : 0.f;
    float hi = tf32_rna(v);
    *(float2*)&dst[(size_t)idx * 2] = make_float2(hi, tf32_rna(v - hi));
}

__global__ void embed_k(const float* __restrict__ emb, const int* __restrict__ x,
                        float* __restrict__ y0s) {
    int idx = blockIdx.x * blockDim.x + threadIdx.x;
    if (idx >= TSZ * BSZ * ESZ) return;
    int e   = idx % ESZ;
    int row = idx / ESZ;
    float v = emb[(size_t)x[row] * ESZ + e];
    float hi = tf32_rna(v);
    *(float2*)&y0s[(size_t)idx * 2] = make_float2(hi, tf32_rna(v - hi));
}

__global__ void wtrans_k(const float* __restrict__ W, float* __restrict__ Wt,
                         int Hp, int Gp) {
    __shared__ float tile[32][33];
    int jblk = blockIdx.x;
    int k0   = blockIdx.y * 32;
    for (int rr = 0; rr < 32; rr += 8) {
        int r = rr + threadIdx.y;
        int g = r >> 3, u = r & 7;
        int j = jblk * 8 + u;
        int orow = g * Hp + j;
        int k = k0 + threadIdx.x;
        tile[r][threadIdx.x] = (j < Hp && k < Hp) ? W[(size_t)orow * Hp + k] : 0.f;
    }
    __syncthreads();
    for (int kk = 0; kk < 32; kk += 8) {
        int k = k0 + kk + threadIdx.y;
        if (k < Hp)
            Wt[(size_t)k * Gp + jblk * 32 + threadIdx.x] = tile[threadIdx.x][kk + threadIdx.y];
    }
}

// ---------------- tf32x2 GEMM: R3 skeleton (BM=128, dbl-buffered) + split operands ----------------
__device__ __forceinline__ void mma_tf32(float4& d, const float* a, const float* b) {
    asm volatile(
        "mma.sync.aligned.m16n8k8.row.col.f32.tf32.tf32.f32 "
        "{%0,%1,%2,%3}, {%4,%5,%6,%7}, {%8,%9}, {%0,%1,%2,%3};\n"
        : "+f"(d.x), "+f"(d.y), "+f"(d.z), "+f"(d.w)
        : "r"(__float_as_uint(a[0])), "r"(__float_as_uint(a[1])),
          "r"(__float_as_uint(a[2])), "r"(__float_as_uint(a[3])),
          "r"(__float_as_uint(b[0])), "r"(__float_as_uint(b[1])));
}

// A_g: [M][2K] split-interleaved; B_g: [N][2K] split-interleaved.
// BM=BN=128, BK=16, 256 threads (8 warps 2m x 4n), warp tile 64x32.
// mode 0: C[m*N + n];  mode 1: C[((b*N + n)*T) + t], m = b*T + t (m-block = one b).
__global__ __launch_bounds__(256, 2)
void gemm_tc(const float* __restrict__ A_g, const float* __restrict__ B_g,
             const float* __restrict__ bias1, const float* __restrict__ bias2,
             float* __restrict__ C, int M, int N, int K, int mode) {
    extern __shared__ float gsm[];
    float* As[2] = {gsm, gsm + 128 * ASTRIDE};
    float* Bs[2] = {gsm + 2 * 128 * ASTRIDE, gsm + 3 * 128 * ASTRIDE};

    const int tid  = threadIdx.x;
    const int lane = tid & 31;
    const int w    = tid >> 5;
    const int wm   = (w & 1) * 64;
    const int wn   = (w >> 1) * 32;
    const int qr   = lane >> 2;
    const int qc   = lane & 3;

    const int m0 = blockIdx.y * 128;
    const int n0 = blockIdx.x * 128;

    const int lrow = tid >> 1;         // 0..127
    const int lk   = (tid & 1) * 8;    // k-offset 0 or 8

    const float* Arow = A_g + (size_t)(m0 + lrow) * (2 * K) + 2 * lk;
    const int bn = n0 + lrow;
    const bool bvalid = bn < N;
    const float* Brow = B_g + (size_t)(bvalid ? bn : 0) * (2 * K) + 2 * lk;

    float4* Adst0 = (float4*)(As[0] + lrow * ASTRIDE + 2 * lk);
    float4* Adst1 = (float4*)(As[1] + lrow * ASTRIDE + 2 * lk);
    float4* Bdst0 = (float4*)(Bs[0] + lrow * ASTRIDE + 2 * lk);
    float4* Bdst1 = (float4*)(Bs[1] + lrow * ASTRIDE + 2 * lk);

    // prologue: slab 0
    {
#pragma unroll
        for (int j = 0; j < 4; j++) {
            Adst0[j] = *(const float4*)(Arow + j * 4);
            Bdst0[j] = bvalid ? *(const float4*)(Brow + j * 4) : make_float4(0.f, 0.f, 0.f, 0.f);
        }
    }
    __syncthreads();

    float4 acc[4][4];
#pragma unroll
    for (int i = 0; i < 4; i++)
#pragma unroll
        for (int j = 0; j < 4; j++) acc[i][j] = make_float4(0.f, 0.f, 0.f, 0.f);

    int buf = 0;
    for (int k0 = 16; k0 <= K; k0 += 16) {
        float4 ra[4], rb[4];
        const bool more = (k0 < K);
        if (more) {
            const float* an = Arow + (size_t)k0 * 2;
            const float* bnp = Brow + (size_t)k0 * 2;
#pragma unroll
            for (int j = 0; j < 4; j++) {
                ra[j] = *(const float4*)(an + j * 4);
                rb[j] = bvalid ? *(const float4*)(bnp + j * 4) : make_float4(0.f, 0.f, 0.f, 0.f);
            }
        }

        const float2* A2 = (const float2*)As[buf];
        const float2* B2 = (const float2*)Bs[buf];
#pragma unroll
        for (int kk = 0; kk < 16; kk += 8) {
            float ah[4][4], al[4][4], bh[4][2], bl[4][2];
#pragma unroll
            for (int mt = 0; mt < 4; mt++) {
                int r = (wm + mt * 16 + qr) * (ASTRIDE / 2) + kk + qc;
                float2 x0 = A2[r];
                float2 x1 = A2[r + 8 * (ASTRIDE / 2)];
                float2 x2 = A2[r + 4];
                float2 x3 = A2[r + 8 * (ASTRIDE / 2) + 4];
                ah[mt][0] = x0.x; al[mt][0] = x0.y;
                ah[mt][1] = x1.x; al[mt][1] = x1.y;
                ah[mt][2] = x2.x; al[mt][2] = x2.y;
                ah[mt][3] = x3.x; al[mt][3] = x3.y;
            }
#pragma unroll
            for (int nt = 0; nt < 4; nt++) {
                int r = (wn + nt * 8 + qr) * (ASTRIDE / 2) + kk + qc;
                float2 x0 = B2[r];
                float2 x1 = B2[r + 4];
                bh[nt][0] = x0.x; bl[nt][0] = x0.y;
                bh[nt][1] = x1.x; bl[nt][1] = x1.y;
            }
#pragma unroll
            for (int mt = 0; mt < 4; mt++)
#pragma unroll
                for (int nt = 0; nt < 4; nt++) {
                    mma_tf32(acc[mt][nt], ah[mt], bh[nt]);
                    mma_tf32(acc[mt][nt], ah[mt], bl[nt]);
                    mma_tf32(acc[mt][nt], al[mt], bh[nt]);
                }
        }

        if (more) {
            int nb = buf ^ 1;
            float4* Ad = nb ? Adst1 : Adst0;
            float4* Bd = nb ? Bdst1 : Bdst0;
#pragma unroll
            for (int j = 0; j < 4; j++) { Ad[j] = ra[j]; Bd[j] = rb[j]; }
            __syncthreads();
            buf = nb;
        }
    }

    // epilogue (R3 layout: warp tile 64x32)
#pragma unroll
    for (int mt = 0; mt < 4; mt++) {
        int mrow = m0 + wm + mt * 16 + qr;
#pragma unroll
        for (int nt = 0; nt < 4; nt++) {
            int n = n0 + wn + nt * 8 + 2 * qc;
            if (n >= N) continue;
            float b0 = 0.f, b1 = 0.f;
            if (bias1) { b0 += bias1[n]; b1 += bias1[n + 1]; }
            if (bias2) { b0 += bias2[n]; b1 += bias2[n + 1]; }
            float4 v = acc[mt][nt];
            if (mode == 0) {
                C[(size_t)mrow * N + n]           = v.x + b0;
                C[(size_t)mrow * N + n + 1]       = v.y + b1;
                C[(size_t)(mrow + 8) * N + n]     = v.z + b0;
                C[(size_t)(mrow + 8) * N + n + 1] = v.w + b1;
            } else {
                int bidx = m0 >> 7;
                int t = mrow - m0;
                size_t base = ((size_t)bidx * N + n) * TSZ + t;
                C[base]           = v.x + b0;
                C[base + TSZ]     = v.y + b1;
                C[base + 8]       = v.z + b0;
                C[base + TSZ + 8] = v.w + b1;
            }
        }
    }
}

// ---------------- persistent LSTM layer kernel (unchanged from R12) ----------------
__device__ __forceinline__ float sigf(float z) { return 1.f / (1.f + expf(-z)); }

#define FMA2(d, a, b) \
    asm("fma.rn.f32x2 %0, %1, %2, %0;" : "+l"(d) : "l"(a), "l"(b))

__device__ __forceinline__ void grid_bar_flags(unsigned* flags, int nCTA, unsigned target) {
    __syncthreads();
    if (threadIdx.x == 0) {
        asm volatile("st.release.gpu.global.u32 [%0], %1;"
                     :: "l"(flags + (size_t)blockIdx.x * FLAGSTRIDE), "r"(target) : "memory");
    }
    if (threadIdx.x < nCTA) {
        unsigned v;
        do {
            asm volatile("ld.acquire.gpu.global.u32 %0, [%1];"
                         : "=r"(v) : "l"(flags + (size_t)threadIdx.x * FLAGSTRIDE) : "memory");
        } while ((int)(v - target) < 0);
    }
    __syncthreads();
}

__global__ __launch_bounds__(512, 1)
void lstm_layer_k(const float* __restrict__ pre, const float* __restrict__ Wt,
                  float* __restrict__ hA, float* __restrict__ hB,
                  float* __restrict__ cOut, float* __restrict__ y,
                  int Hp, int Gp, int ldy, unsigned* flags) {
    extern __shared__ float sm[];
    float* sW   = sm;
    float* red  = sm + Hp * 32;
    float* gsum = red + NSL * 32 * 16;
    float* cT   = gsum + 512;
    unsigned* sbase = (unsigned*)(cT + 128);

    const int tid  = threadIdx.x;
    const int jblk = blockIdx.x;
    const int nCTA = gridDim.x;
    const int lane = tid & 31;
    const int s    = tid >> 5;
    const int bg   = lane >> 3;
    const int cg   = lane & 7;
    const int G4 = 4 * Hp;

    const int p_out = tid >> 2;
    const int p_g   = tid & 3;
    const int p_eb  = p_out & 15;
    const int p_eu  = p_out >> 4;
    const int p_ej  = jblk * 8 + p_eu;
    const bool p_act = p_ej < Hp;
    const int p_ebg = p_eb >> 2, p_ebi = p_eb & 3;
    const int p_co  = p_g * 8 + p_eu;
    const int p_cg2 = p_co >> 2, p_c2 = p_co & 3;

    const int eb = tid & 15;
    const int eu = tid >> 4;
    const int ej = jblk * 8 + eu;
    const bool eact = (tid < 128) && (ej < Hp);
    const bool epad = (tid < 128) && (ej >= Hp) && (ej < ldy);

    if (tid == 0) *sbase = flags[(size_t)jblk * FLAGSTRIDE];
    for (int idx = tid; idx < Hp * 32; idx += 512) {
        int k = idx >> 5, rr = idx & 31;
        sW[idx] = Wt[(size_t)k * Gp + jblk * 32 + rr];
    }
    if (tid < 128) {
        cT[tid] = 0.f;
        if (ej < Hp) hA[ej * 16 + eb] = 0.f;
    }
    __syncthreads();
    const unsigned base = *sbase;

    float pg = 0.f;
    if (p_act)
        pg = __ldcg(pre + ((size_t)p_eb * TSZ + 0) * G4 + (size_t)p_g * Hp + p_ej);

    grid_bar_flags(flags, nCTA, base + 1u);

    const float4* sW4base = (const float4*)sW;

    for (int t = 0; t < TSZ; t++) {
        const float* hin = (t & 1) ? hB : hA;
        float* hout      = (t & 1) ? hA : hB;

        unsigned long long acc2[8];
#pragma unroll
        for (int i = 0; i < 8; i++) acc2[i] = 0ULL;

        const ulonglong2* hv = (const ulonglong2*)hin;
#pragma unroll 8
        for (int k = s; k < Hp; k += NSL) {
            float4 wq = sW4base[k * 8 + cg];
            ulonglong2 hp = hv[k * 4 + bg];
            unsigned long long w0, w1, w2, w3;
            asm("mov.b64 %0, {%1, %1};" : "=l"(w0) : "r"(__float_as_uint(wq.x)));
            asm("mov.b64 %0, {%1, %1};" : "=l"(w1) : "r"(__float_as_uint(wq.y)));
            asm("mov.b64 %0, {%1, %1};" : "=l"(w2) : "r"(__float_as_uint(wq.z)));
            asm("mov.b64 %0, {%1, %1};" : "=l"(w3) : "r"(__float_as_uint(wq.w)));
            FMA2(acc2[0], w0, hp.x); FMA2(acc2[1], w0, hp.y);
            FMA2(acc2[2], w1, hp.x); FMA2(acc2[3], w1, hp.y);
            FMA2(acc2[4], w2, hp.x); FMA2(acc2[5], w2, hp.y);
            FMA2(acc2[6], w3, hp.x); FMA2(acc2[7], w3, hp.y);
        }

        ulonglong2* rp = (ulonglong2*)&red[(s * 32 + lane) * 16];
        rp[0] = make_ulonglong2(acc2[0], acc2[1]);
        rp[1] = make_ulonglong2(acc2[2], acc2[3]);
        rp[2] = make_ulonglong2(acc2[4], acc2[5]);
        rp[3] = make_ulonglong2(acc2[6], acc2[7]);
        __syncthreads();

        {
            float sum = pg;
            int ridx = (p_ebg * 8 + p_cg2) * 16 + p_c2 * 4 + p_ebi;
#pragma unroll
            for (int s2 = 0; s2 < NSL; s2++)
                sum += red[s2 * 512 + ridx];
            gsum[tid] = sum;
        }
        __syncthreads();

        if (eact) {
            float4 gv = *(const float4*)&gsum[tid * 4];
            float ig = sigf(gv.x);
            float fg = sigf(gv.y);
            float gg = tanhf(gv.z);
            float og = sigf(gv.w);
            float c  = fg * cT[tid] + ig * gg;
            float hn = og * tanhf(c);
            cT[tid] = c;
            __stcg(&hout[ej * 16 + eb], hn);
            float yhi = tf32_rna(hn);
            *(float2*)&y[(((size_t)eb * TSZ + t) * ldy + ej) * 2] =
                make_float2(yhi, tf32_rna(hn - yhi));
            if (t == TSZ - 1) cOut[ej * 16 + eb] = c;
        } else if (epad) {
            *(float2*)&y[(((size_t)eb * TSZ + t) * ldy + ej) * 2] = make_float2(0.f, 0.f);
        }

        float pgn = 0.f;
        if (p_act && t + 1 < TSZ)
            pgn = __ldcg(pre + ((size_t)p_eb * TSZ + t + 1) * G4 + (size_t)p_g * Hp + p_ej);

        grid_bar_flags(flags, nCTA, base + (unsigned)(t + 2));
        pg = pgn;
    }
}

// ---------------- finalize ----------------
__global__ void finalize_k(const float* __restrict__ y1s, const float* __restrict__ y2s,
                           const float* __restrict__ y3s, const float* __restrict__ cT1,
                           const float* __restrict__ cT2, const float* __restrict__ cT3,
                           float* __restrict__ out) {
    int i = blockIdx.x * blockDim.x + threadIdx.x;
    if (i >= 86400) return;
    const size_t O = (size_t)BSZ * VSZ * TSZ;
    if (i < 18400) {
        int b = i / 1150, j = i % 1150;
        size_t p = (((size_t)b * TSZ + 127) * HPAD + j) * 2;
        out[O + i] = y1s[p] + y1s[p + 1];
    } else if (i < 36800) {
        int k = i - 18400; int b = k / 1150, j = k % 1150;
        size_t p = (((size_t)b * TSZ + 127) * HPAD + j) * 2;
        out[O + i] = y2s[p] + y2s[p + 1];
    } else if (i < 43200) {
        int k = i - 36800; int b = k / 400, j = k % 400;
        size_t p = (((size_t)b * TSZ + 127) * 400 + j) * 2;
        out[O + i] = y3s[p] + y3s[p + 1];
    } else if (i < 61600) {
        int k = i - 43200; int j = (k % 1150), b = k / 1150;
        out[O + i] = cT1[j * 16 + b];
    } else if (i < 80000) {
        int k = i - 61600; int j = (k % 1150), b = k / 1150;
        out[O + i] = cT2[j * 16 + b];
    } else {
        int k = i - 80000; int j = (k % 400), b = k / 400;
        out[O + i] = cT3[j * 16 + b];
    }
}

// ---------------- launch ----------------
extern "C" void kernel_launch(void* const* d_in, const int* in_sizes, int n_in,
                              void* d_out, int out_size) {
    const float* emb  = (const float*)d_in[0];
    const float* Wih1 = (const float*)d_in[1];
    const float* Whh1 = (const float*)d_in[2];
    const float* bih1 = (const float*)d_in[3];
    const float* bhh1 = (const float*)d_in[4];
    const float* Wih2 = (const float*)d_in[5];
    const float* Whh2 = (const float*)d_in[6];
    const float* bih2 = (const float*)d_in[7];
    const float* bhh2 = (const float*)d_in[8];
    const float* Wih3 = (const float*)d_in[9];
    const float* Whh3 = (const float*)d_in[10];
    const float* bih3 = (const float*)d_in[11];
    const float* bhh3 = (const float*)d_in[12];
    const float* linb = (const float*)d_in[13];
    const int*   x    = (const int*)d_in[14];
    float* out = (float*)d_out;

    float *y0s, *y1s, *y2s, *y3s, *pre, *Wt1, *Wt2, *Wt3, *W1s, *W2s, *W3s, *embs;
    float *hTa, *hTb, *cT1, *cT2, *cT3;
    unsigned* flags;
    cudaGetSymbolAddress((void**)&y0s, g_y0s);
    cudaGetSymbolAddress((void**)&y1s, g_y1s);
    cudaGetSymbolAddress((void**)&y2s, g_y2s);
    cudaGetSymbolAddress((void**)&y3s, g_y3s);
    cudaGetSymbolAddress((void**)&pre, g_pre);
    cudaGetSymbolAddress((void**)&Wt1, g_Wt1);
    cudaGetSymbolAddress((void**)&Wt2, g_Wt2);
    cudaGetSymbolAddress((void**)&Wt3, g_Wt3);
    cudaGetSymbolAddress((void**)&W1s, g_W1s);
    cudaGetSymbolAddress((void**)&W2s, g_W2s);
    cudaGetSymbolAddress((void**)&W3s, g_W3s);
    cudaGetSymbolAddress((void**)&embs, g_embs);
    cudaGetSymbolAddress((void**)&hTa, g_hTa);
    cudaGetSymbolAddress((void**)&hTb, g_hTb);
    cudaGetSymbolAddress((void**)&cT1, g_cT1);
    cudaGetSymbolAddress((void**)&cT2, g_cT2);
    cudaGetSymbolAddress((void**)&cT3, g_cT3);
    cudaGetSymbolAddress((void**)&flags, g_flags);

    const int M = TSZ * BSZ;  // 2048
    const int SMEM12 = (HSZ * 32 + NSL * 32 * 16 + 512 + 128 + 32) * 4;
    const int SMEM3  = (ESZ * 32 + NSL * 32 * 16 + 512 + 128 + 32) * 4;
    static int smem_set = 0;
    if (!smem_set) {
        cudaFuncSetAttribute(lstm_layer_k, cudaFuncAttributeMaxDynamicSharedMemorySize, SMEM12);
        cudaFuncSetAttribute(gemm_tc, cudaFuncAttributeMaxDynamicSharedMemorySize, GEMM_SMEM);
        smem_set = 1;
    }

    // ----- layer 1: embed -> wtrans1 -> splitW1 -> gemm1 (4th launch: profiled) -----
    embed_k<<<(TSZ * BSZ * ESZ + 255) / 256, 256>>>(emb, x, y0s);
    wtrans_k<<<dim3(GP12 / 32, (HSZ + 31) / 32), dim3(32, 8)>>>(Whh1, Wt1, HSZ, GP12);
    split_k<<<(4 * HSZ * ESZ + 255) / 256, 256>>>(Wih1, W1s, 4 * HSZ * ESZ);
    gemm_tc<<<dim3((4 * HSZ + 127) / 128, M / 128), 256, GEMM_SMEM>>>(
        y0s, W1s, bih1, bhh1, pre, M, 4 * HSZ, ESZ, 0);
    lstm_layer_k<<<GP12 / 32, 512, SMEM12>>>(pre, Wt1, hTa, hTb, cT1, y1s,
                                             HSZ, GP12, HPAD, flags + 0 * 144 * FLAGSTRIDE);

    // ----- layer 2 -----
    padsplit_k<<<(4 * HSZ * HPAD + 255) / 256, 256>>>(Wih2, W2s, 4 * HSZ, HSZ, HPAD);
    wtrans_k<<<dim3(GP12 / 32, (HSZ + 31) / 32), dim3(32, 8)>>>(Whh2, Wt2, HSZ, GP12);
    gemm_tc<<<dim3((4 * HSZ + 127) / 128, M / 128), 256, GEMM_SMEM>>>(
        y1s, W2s, bih2, bhh2, pre, M, 4 * HSZ, HPAD, 0);
    lstm_layer_k<<<GP12 / 32, 512, SMEM12>>>(pre, Wt2, hTa, hTb, cT2, y2s,
                                             HSZ, GP12, HPAD, flags + 1 * 144 * FLAGSTRIDE);

    // ----- layer 3 -----
    padsplit_k<<<(4 * ESZ * HPAD + 255) / 256, 256>>>(Wih3, W3s, 4 * ESZ, HSZ, HPAD);
    wtrans_k<<<dim3(GP3 / 32, (ESZ + 31) / 32), dim3(32, 8)>>>(Whh3, Wt3, ESZ, GP3);
    gemm_tc<<<dim3((4 * ESZ + 127) / 128, M / 128), 256, GEMM_SMEM>>>(
        y2s, W3s, bih3, bhh3, pre, M, 4 * ESZ, HPAD, 0);
    lstm_layer_k<<<GP3 / 32, 512, SMEM3>>>(pre, Wt3, hTa, hTb, cT3, y3s,
                                           ESZ, GP3, ESZ, flags + 2 * 144 * FLAGSTRIDE);

    // ----- tied output projection into (B,V,T) -----
    split_k<<<(VSZ * ESZ + 255) / 256, 256>>>(emb, embs, VSZ * ESZ);
    gemm_tc<<<dim3(VSZ / 128, M / 128), 256, GEMM_SMEM>>>(
        y3s, embs, linb, nullptr, out, M, VSZ, ESZ, 1);

    // ----- final states -----
    finalize_k<<<(86400 + 255) / 256, 256>>>(y1s, y2s, y3s, cT1, cT2, cT3, out);
}

// round 14
// speedup vs baseline: 1.2190x; 1.2190x over previous
#include <cuda_runtime.h>
#include <stdint.h>
#include <math.h>

#define VSZ 32000
#define ESZ 400
#define HSZ 1150
#define HPAD 1152
#define BSZ 16
#define TSZ 128
#define GP12 4608
#define GP3  1600
#define FLAGSTRIDE 32
#define NSL 16

// ---------------- scratch ----------------
__device__ float g_y0[TSZ*BSZ*ESZ];
__device__ float g_y1[TSZ*BSZ*HPAD];
__device__ float g_y2[TSZ*BSZ*HPAD];
__device__ float g_y3[TSZ*BSZ*ESZ];
__device__ float g_pre[TSZ*BSZ*4*HSZ];
__device__ float g_Wt1[HSZ*GP12];
__device__ float g_Wt2[HSZ*GP12];
__device__ float g_Wt3[ESZ*GP3];
__device__ float g_Wih2p[4*HSZ*HPAD];
__device__ float g_Wih3p[4*ESZ*HPAD];
__device__ float g_hTa[HSZ*BSZ];
__device__ float g_hTb[HSZ*BSZ];
__device__ float g_cT1[HSZ*BSZ];
__device__ float g_cT2[HSZ*BSZ];
__device__ float g_cT3[ESZ*BSZ];
__device__ unsigned g_flags[3 * 144 * FLAGSTRIDE];

// ---------------- tiny utility kernels ----------------
__global__ void pad_k(const float* __restrict__ src, float* __restrict__ dst,
                      int rows, int Kin, int Kout) {
    int idx = blockIdx.x * blockDim.x + threadIdx.x;
    if (idx >= rows * Kout) return;
    int r = idx / Kout, k = idx % Kout;
    dst[idx] = (k < Kin) ? src[(size_t)r * Kin + k] : 0.f;
}

__global__ void embed_k(const float* __restrict__ emb, const int* __restrict__ x,
                        float* __restrict__ y0) {
    int idx = blockIdx.x * blockDim.x + threadIdx.x;
    if (idx >= TSZ * BSZ * ESZ) return;
    int e   = idx % ESZ;
    int row = idx / ESZ;
    y0[idx] = emb[(size_t)x[row] * ESZ + e];
}

__global__ void wtrans_k(const float* __restrict__ W, float* __restrict__ Wt,
                         int Hp, int Gp) {
    __shared__ float tile[32][33];
    int jblk = blockIdx.x;
    int k0   = blockIdx.y * 32;
    for (int rr = 0; rr < 32; rr += 8) {
        int r = rr + threadIdx.y;
        int g = r >> 3, u = r & 7;
        int j = jblk * 8 + u;
        int orow = g * Hp + j;
        int k = k0 + threadIdx.x;
        tile[r][threadIdx.x] = (j < Hp && k < Hp) ? W[(size_t)orow * Hp + k] : 0.f;
    }
    __syncthreads();
    for (int kk = 0; kk < 32; kk += 8) {
        int k = k0 + kk + threadIdx.y;
        if (k < Hp)
            Wt[(size_t)k * Gp + jblk * 32 + threadIdx.x] = tile[threadIdx.x][kk + threadIdx.y];
    }
}

// ---------------- tf32x2 tensor-core GEMM (R3 config: measured 157us) ----------------
__device__ __forceinline__ float tf32_rna(float x) {
    float r;
    asm("cvt.rna.tf32.f32 %0, %1;" : "=f"(r) : "f"(x));
    return r;
}

__device__ __forceinline__ void mma_tf32(float4& d, const float* a, const float* b) {
    asm volatile(
        "mma.sync.aligned.m16n8k8.row.col.f32.tf32.tf32.f32 "
        "{%0,%1,%2,%3}, {%4,%5,%6,%7}, {%8,%9}, {%0,%1,%2,%3};\n"
        : "+f"(d.x), "+f"(d.y), "+f"(d.z), "+f"(d.w)
        : "r"(__float_as_uint(a[0])), "r"(__float_as_uint(a[1])),
          "r"(__float_as_uint(a[2])), "r"(__float_as_uint(a[3])),
          "r"(__float_as_uint(b[0])), "r"(__float_as_uint(b[1])));
}

#define SSTR 20

__global__ __launch_bounds__(256)
void gemm_tc(const float* __restrict__ A, const float* __restrict__ Bm,
             const float* __restrict__ bias1, const float* __restrict__ bias2,
             float* __restrict__ C, int M, int N, int K, int mode) {
    __shared__ float As[2][128 * SSTR];
    __shared__ float Bs[2][128 * SSTR];

    const int tid  = threadIdx.x;
    const int lane = tid & 31;
    const int w    = tid >> 5;
    const int wm   = (w & 1) * 64;
    const int wn   = (w >> 1) * 32;
    const int qr   = lane >> 2;
    const int qc   = lane & 3;

    const int m0 = blockIdx.y * 128;
    const int n0 = blockIdx.x * 128;

    const int lrow = tid >> 1;
    const int lk   = (tid & 1) * 8;

    const float* Aptr = A + (size_t)(m0 + lrow) * K + lk;
    const float* Bptr = Bm + (size_t)(n0 + lrow) * K + lk;
    const bool bvalid = (n0 + lrow) < N;

    float4 acc[4][4];
#pragma unroll
    for (int i = 0; i < 4; i++)
#pragma unroll
        for (int j = 0; j < 4; j++) acc[i][j] = make_float4(0.f, 0.f, 0.f, 0.f);

    for (int k0 = 0; k0 < K; k0 += 16) {
        float4 av0 = *(const float4*)(Aptr + k0);
        float4 av1 = *(const float4*)(Aptr + k0 + 4);
        float4 bv0 = bvalid ? *(const float4*)(Bptr + k0) : make_float4(0.f, 0.f, 0.f, 0.f);
        float4 bv1 = bvalid ? *(const float4*)(Bptr + k0 + 4) : make_float4(0.f, 0.f, 0.f, 0.f);
        __syncthreads();
        {
            float va[8] = {av0.x, av0.y, av0.z, av0.w, av1.x, av1.y, av1.z, av1.w};
            float vb[8] = {bv0.x, bv0.y, bv0.z, bv0.w, bv1.x, bv1.y, bv1.z, bv1.w};
            int base = lrow * SSTR + lk;
#pragma unroll
            for (int j = 0; j < 8; j++) {
                float hi = tf32_rna(va[j]);
                As[0][base + j] = hi;
                As[1][base + j] = tf32_rna(va[j] - hi);
                float bhi = tf32_rna(vb[j]);
                Bs[0][base + j] = bhi;
                Bs[1][base + j] = tf32_rna(vb[j] - bhi);
            }
        }
        __syncthreads();

#pragma unroll
        for (int kk = 0; kk < 16; kk += 8) {
            float ah[4][4], al[4][4], bh[4][2], bl[4][2];
#pragma unroll
            for (int mt = 0; mt < 4; mt++) {
                int base = (wm + mt * 16 + qr) * SSTR + kk + qc;
                ah[mt][0] = As[0][base];
                ah[mt][1] = As[0][base + 8 * SSTR];
                ah[mt][2] = As[0][base + 4];
                ah[mt][3] = As[0][base + 8 * SSTR + 4];
                al[mt][0] = As[1][base];
                al[mt][1] = As[1][base + 8 * SSTR];
                al[mt][2] = As[1][base + 4];
                al[mt][3] = As[1][base + 8 * SSTR + 4];
            }
#pragma unroll
            for (int nt = 0; nt < 4; nt++) {
                int base = (wn + nt * 8 + qr) * SSTR + kk + qc;
                bh[nt][0] = Bs[0][base];
                bh[nt][1] = Bs[0][base + 4];
                bl[nt][0] = Bs[1][base];
                bl[nt][1] = Bs[1][base + 4];
            }
#pragma unroll
            for (int mt = 0; mt < 4; mt++)
#pragma unroll
                for (int nt = 0; nt < 4; nt++) {
                    mma_tf32(acc[mt][nt], ah[mt], bh[nt]);
                    mma_tf32(acc[mt][nt], ah[mt], bl[nt]);
                    mma_tf32(acc[mt][nt], al[mt], bh[nt]);
                }
        }
    }

#pragma unroll
    for (int mt = 0; mt < 4; mt++) {
        int mrow = m0 + wm + mt * 16 + qr;
#pragma unroll
        for (int nt = 0; nt < 4; nt++) {
            int n = n0 + wn + nt * 8 + 2 * qc;
            if (n >= N) continue;
            float b0 = 0.f, b1 = 0.f;
            if (bias1) { b0 += bias1[n]; b1 += bias1[n + 1]; }
            if (bias2) { b0 += bias2[n]; b1 += bias2[n + 1]; }
            float4 v = acc[mt][nt];
            if (mode == 0) {
                C[(size_t)mrow * N + n]           = v.x + b0;
                C[(size_t)mrow * N + n + 1]       = v.y + b1;
                C[(size_t)(mrow + 8) * N + n]     = v.z + b0;
                C[(size_t)(mrow + 8) * N + n + 1] = v.w + b1;
            } else {
                int bidx = m0 >> 7;
                int t = (mrow - m0);
                size_t base = ((size_t)bidx * N + n) * TSZ + t;
                C[base]           = v.x + b0;
                C[base + TSZ]     = v.y + b1;
                C[base + 8]       = v.z + b0;
                C[base + TSZ + 8] = v.w + b1;
            }
        }
    }
}

// ---------------- persistent LSTM layer kernel (R9 config + pre-prefetch) ----------------
__device__ __forceinline__ float sigf(float z) { return 1.f / (1.f + expf(-z)); }

#define FMA2(d, a, b) \
    asm("fma.rn.f32x2 %0, %1, %2, %0;" : "+l"(d) : "l"(a), "l"(b))

__device__ __forceinline__ void grid_bar_flags(unsigned* flags, int nCTA, unsigned target) {
    __syncthreads();
    if (threadIdx.x == 0) {
        asm volatile("st.release.gpu.global.u32 [%0], %1;"
                     :: "l"(flags + (size_t)blockIdx.x * FLAGSTRIDE), "r"(target) : "memory");
    }
    if (threadIdx.x < nCTA) {
        unsigned v;
        do {
            asm volatile("ld.acquire.gpu.global.u32 %0, [%1];"
                         : "=r"(v) : "l"(flags + (size_t)threadIdx.x * FLAGSTRIDE) : "memory");
        } while ((int)(v - target) < 0);
    }
    __syncthreads();
}

__global__ __launch_bounds__(512, 1)
void lstm_layer_k(const float* __restrict__ pre, const float* __restrict__ Wt,
                  float* __restrict__ hA, float* __restrict__ hB,
                  float* __restrict__ cOut, float* __restrict__ y,
                  int Hp, int Gp, int ldy, unsigned* flags) {
    extern __shared__ float sm[];
    float* sW   = sm;
    float* red  = sm + Hp * 32;
    float* gsum = red + NSL * 32 * 16;
    float* cT   = gsum + 512;
    unsigned* sbase = (unsigned*)(cT + 128);

    const int tid  = threadIdx.x;
    const int jblk = blockIdx.x;
    const int nCTA = gridDim.x;
    const int lane = tid & 31;
    const int s    = tid >> 5;
    const int bg   = lane >> 3;
    const int cg   = lane & 7;
    const int G4 = 4 * Hp;

    const int p_out = tid >> 2;
    const int p_g   = tid & 3;
    const int p_eb  = p_out & 15;
    const int p_eu  = p_out >> 4;
    const int p_ej  = jblk * 8 + p_eu;
    const bool p_act = p_ej < Hp;
    const int p_ebg = p_eb >> 2, p_ebi = p_eb & 3;
    const int p_co  = p_g * 8 + p_eu;
    const int p_cg2 = p_co >> 2, p_c2 = p_co & 3;

    const int eb = tid & 15;
    const int eu = tid >> 4;
    const int ej = jblk * 8 + eu;
    const bool eact = (tid < 128) && (ej < Hp);
    const bool epad = (tid < 128) && (ej >= Hp) && (ej < ldy);

    if (tid == 0) *sbase = flags[(size_t)jblk * FLAGSTRIDE];
    for (int idx = tid; idx < Hp * 32; idx += 512) {
        int k = idx >> 5, rr = idx & 31;
        sW[idx] = Wt[(size_t)k * Gp + jblk * 32 + rr];
    }
    if (tid < 128) {
        cT[tid] = 0.f;
        if (ej < Hp) hA[ej * 16 + eb] = 0.f;
    }
    __syncthreads();
    const unsigned base = *sbase;

    // prefetch step-0 pre value before the barrier (independent of h)
    float pg = 0.f;
    if (p_act)
        pg = __ldcg(pre + ((size_t)p_eb * TSZ + 0) * G4 + (size_t)p_g * Hp + p_ej);

    grid_bar_flags(flags, nCTA, base + 1u);

    const float4* sW4base = (const float4*)sW;

    for (int t = 0; t < TSZ; t++) {
        const float* hin = (t & 1) ? hB : hA;
        float* hout      = (t & 1) ? hA : hB;

        unsigned long long acc2[8];
#pragma unroll
        for (int i = 0; i < 8; i++) acc2[i] = 0ULL;

        const ulonglong2* hv = (const ulonglong2*)hin;
#pragma unroll 8
        for (int k = s; k < Hp; k += NSL) {
            float4 wq = sW4base[k * 8 + cg];
            ulonglong2 hp = hv[k * 4 + bg];
            unsigned long long w0, w1, w2, w3;
            asm("mov.b64 %0, {%1, %1};" : "=l"(w0) : "r"(__float_as_uint(wq.x)));
            asm("mov.b64 %0, {%1, %1};" : "=l"(w1) : "r"(__float_as_uint(wq.y)));
            asm("mov.b64 %0, {%1, %1};" : "=l"(w2) : "r"(__float_as_uint(wq.z)));
            asm("mov.b64 %0, {%1, %1};" : "=l"(w3) : "r"(__float_as_uint(wq.w)));
            FMA2(acc2[0], w0, hp.x); FMA2(acc2[1], w0, hp.y);
            FMA2(acc2[2], w1, hp.x); FMA2(acc2[3], w1, hp.y);
            FMA2(acc2[4], w2, hp.x); FMA2(acc2[5], w2, hp.y);
            FMA2(acc2[6], w3, hp.x); FMA2(acc2[7], w3, hp.y);
        }

        ulonglong2* rp = (ulonglong2*)&red[(s * 32 + lane) * 16];
        rp[0] = make_ulonglong2(acc2[0], acc2[1]);
        rp[1] = make_ulonglong2(acc2[2], acc2[3]);
        rp[2] = make_ulonglong2(acc2[4], acc2[5]);
        rp[3] = make_ulonglong2(acc2[6], acc2[7]);
        __syncthreads();

        {
            float sum = pg;
            int ridx = (p_ebg * 8 + p_cg2) * 16 + p_c2 * 4 + p_ebi;
#pragma unroll
            for (int s2 = 0; s2 < NSL; s2++)
                sum += red[s2 * 512 + ridx];
            gsum[tid] = sum;
        }
        __syncthreads();

        if (eact) {
            float4 gv = *(const float4*)&gsum[tid * 4];
            float ig = sigf(gv.x);
            float fg = sigf(gv.y);
            float gg = tanhf(gv.z);
            float og = sigf(gv.w);
            float c  = fg * cT[tid] + ig * gg;
            float hn = og * tanhf(c);
            cT[tid] = c;
            __stcg(&hout[ej * 16 + eb], hn);
            y[((size_t)eb * TSZ + t) * ldy + ej] = hn;
            if (t == TSZ - 1) cOut[ej * 16 + eb] = c;
        } else if (epad) {
            y[((size_t)eb * TSZ + t) * ldy + ej] = 0.f;
        }

        // prefetch next step's pre value before the barrier
        float pgn = 0.f;
        if (p_act && t + 1 < TSZ)
            pgn = __ldcg(pre + ((size_t)p_eb * TSZ + t + 1) * G4 + (size_t)p_g * Hp + p_ej);

        grid_bar_flags(flags, nCTA, base + (unsigned)(t + 2));
        pg = pgn;
    }
}

// ---------------- finalize ----------------
__global__ void finalize_k(const float* __restrict__ y1, const float* __restrict__ y2,
                           const float* __restrict__ y3, const float* __restrict__ cT1,
                           const float* __restrict__ cT2, const float* __restrict__ cT3,
                           float* __restrict__ out) {
    int i = blockIdx.x * blockDim.x + threadIdx.x;
    if (i >= 86400) return;
    const size_t O = (size_t)BSZ * VSZ * TSZ;
    if (i < 18400) {
        int b = i / 1150, j = i % 1150;
        out[O + i] = y1[((size_t)b * TSZ + 127) * HPAD + j];
    } else if (i < 36800) {
        int k = i - 18400; int b = k / 1150, j = k % 1150;
        out[O + i] = y2[((size_t)b * TSZ + 127) * HPAD + j];
    } else if (i < 43200) {
        int k = i - 36800; int b = k / 400, j = k % 400;
        out[O + i] = y3[((size_t)b * TSZ + 127) * 400 + j];
    } else if (i < 61600) {
        int k = i - 43200; int j = (k % 1150), b = k / 1150;
        out[O + i] = cT1[j * 16 + b];
    } else if (i < 80000) {
        int k = i - 61600; int j = (k % 1150), b = k / 1150;
        out[O + i] = cT2[j * 16 + b];
    } else {
        int k = i - 80000; int j = (k % 400), b = k / 400;
        out[O + i] = cT3[j * 16 + b];
    }
}

// ---------------- launch ----------------
extern "C" void kernel_launch(void* const* d_in, const int* in_sizes, int n_in,
                              void* d_out, int out_size) {
    const float* emb  = (const float*)d_in[0];
    const float* Wih1 = (const float*)d_in[1];
    const float* Whh1 = (const float*)d_in[2];
    const float* bih1 = (const float*)d_in[3];
    const float* bhh1 = (const float*)d_in[4];
    const float* Wih2 = (const float*)d_in[5];
    const float* Whh2 = (const float*)d_in[6];
    const float* bih2 = (const float*)d_in[7];
    const float* bhh2 = (const float*)d_in[8];
    const float* Wih3 = (const float*)d_in[9];
    const float* Whh3 = (const float*)d_in[10];
    const float* bih3 = (const float*)d_in[11];
    const float* bhh3 = (const float*)d_in[12];
    const float* linb = (const float*)d_in[13];
    const int*   x    = (const int*)d_in[14];
    float* out = (float*)d_out;

    float *y0, *y1, *y2, *y3, *pre, *Wt1, *Wt2, *Wt3, *W2p, *W3p;
    float *hTa, *hTb, *cT1, *cT2, *cT3;
    unsigned* flags;
    cudaGetSymbolAddress((void**)&y0,  g_y0);
    cudaGetSymbolAddress((void**)&y1,  g_y1);
    cudaGetSymbolAddress((void**)&y2,  g_y2);
    cudaGetSymbolAddress((void**)&y3,  g_y3);
    cudaGetSymbolAddress((void**)&pre, g_pre);
    cudaGetSymbolAddress((void**)&Wt1, g_Wt1);
    cudaGetSymbolAddress((void**)&Wt2, g_Wt2);
    cudaGetSymbolAddress((void**)&Wt3, g_Wt3);
    cudaGetSymbolAddress((void**)&W2p, g_Wih2p);
    cudaGetSymbolAddress((void**)&W3p, g_Wih3p);
    cudaGetSymbolAddress((void**)&hTa, g_hTa);
    cudaGetSymbolAddress((void**)&hTb, g_hTb);
    cudaGetSymbolAddress((void**)&cT1, g_cT1);
    cudaGetSymbolAddress((void**)&cT2, g_cT2);
    cudaGetSymbolAddress((void**)&cT3, g_cT3);
    cudaGetSymbolAddress((void**)&flags, g_flags);

    const int M = TSZ * BSZ;  // 2048
    const int SMEM12 = (HSZ * 32 + NSL * 32 * 16 + 512 + 128 + 32) * 4;
    const int SMEM3  = (ESZ * 32 + NSL * 32 * 16 + 512 + 128 + 32) * 4;
    static int smem_set = 0;
    if (!smem_set) {
        cudaFuncSetAttribute(lstm_layer_k, cudaFuncAttributeMaxDynamicSharedMemorySize, SMEM12);
        smem_set = 1;
    }

    // ----- layer 1: embed -> wtrans1 -> gemm1 (4th launch: profiled) -----
    embed_k<<<(TSZ * BSZ * ESZ + 255) / 256, 256>>>(emb, x, y0);
    wtrans_k<<<dim3(GP12 / 32, (HSZ + 31) / 32), dim3(32, 8)>>>(Whh1, Wt1, HSZ, GP12);
    wtrans_k<<<dim3(GP12 / 32, (HSZ + 31) / 32), dim3(32, 8)>>>(Whh2, Wt2, HSZ, GP12);
    gemm_tc<<<dim3((4 * HSZ + 127) / 128, M / 128), 256>>>(y0, Wih1, bih1, bhh1, pre,
                                                           M, 4 * HSZ, ESZ, 0);
    lstm_layer_k<<<GP12 / 32, 512, SMEM12>>>(pre, Wt1, hTa, hTb, cT1, y1,
                                             HSZ, GP12, HPAD, flags + 0 * 144 * FLAGSTRIDE);

    // ----- layer 2 -----
    pad_k<<<(4 * HSZ * HPAD + 255) / 256, 256>>>(Wih2, W2p, 4 * HSZ, HSZ, HPAD);
    gemm_tc<<<dim3((4 * HSZ + 127) / 128, M / 128), 256>>>(y1, W2p, bih2, bhh2, pre,
                                                           M, 4 * HSZ, HPAD, 0);
    lstm_layer_k<<<GP12 / 32, 512, SMEM12>>>(pre, Wt2, hTa, hTb, cT2, y2,
                                             HSZ, GP12, HPAD, flags + 1 * 144 * FLAGSTRIDE);

    // ----- layer 3 -----
    pad_k<<<(4 * ESZ * HPAD + 255) / 256, 256>>>(Wih3, W3p, 4 * ESZ, HSZ, HPAD);
    wtrans_k<<<dim3(GP3 / 32, (ESZ + 31) / 32), dim3(32, 8)>>>(Whh3, Wt3, ESZ, GP3);
    gemm_tc<<<dim3((4 * ESZ + 127) / 128, M / 128), 256>>>(y2, W3p, bih3, bhh3, pre,
                                                           M, 4 * ESZ, HPAD, 0);
    lstm_layer_k<<<GP3 / 32, 512, SMEM3>>>(pre, Wt3, hTa, hTb, cT3, y3,
                                           ESZ, GP3, ESZ, flags + 2 * 144 * FLAGSTRIDE);

    // ----- tied output projection into (B,V,T) -----
    gemm_tc<<<dim3(VSZ / 128, M / 128), 256>>>(y3, emb, linb, nullptr, out,
                                               M, VSZ, ESZ, 1);

    // ----- final states -----
    finalize_k<<<(86400 + 255) / 256, 256>>>(y1, y2, y3, cT1, cT2, cT3, out);
}

// round 15
// speedup vs baseline: 1.4256x; 1.1695x over previous
#include <cuda_runtime.h>
#include <stdint.h>
#include <math.h>

#define VSZ 32000
#define ESZ 400
#define HSZ 1150
#define HPAD 1152
#define BSZ 16
#define TSZ 128
#define GP12 4608
#define GP3  1600
#define FLAGSTRIDE 32
#define NSL 16

// ---------------- scratch ----------------
__device__ float g_y0[TSZ*BSZ*ESZ];
__device__ float g_y1[TSZ*BSZ*HPAD];
__device__ float g_y2[TSZ*BSZ*HPAD];
__device__ float g_y3[TSZ*BSZ*ESZ];
__device__ float g_pre[TSZ*BSZ*4*HSZ];
__device__ float g_Wt1[HSZ*GP12];
__device__ float g_Wt2[HSZ*GP12];
__device__ float g_Wt3[ESZ*GP3];
__device__ float g_Wih2p[4*HSZ*HPAD];
__device__ float g_Wih3p[4*ESZ*HPAD];
__device__ float g_hTa[HSZ*BSZ];
__device__ float g_hTb[HSZ*BSZ];
__device__ float g_cT1[HSZ*BSZ];
__device__ float g_cT2[HSZ*BSZ];
__device__ float g_cT3[ESZ*BSZ];
__device__ unsigned g_flags[3 * 144 * FLAGSTRIDE];

// ---------------- tiny utility kernels ----------------
__global__ void pad_k(const float* __restrict__ src, float* __restrict__ dst,
                      int rows, int Kin, int Kout) {
    int idx = blockIdx.x * blockDim.x + threadIdx.x;
    if (idx >= rows * Kout) return;
    int r = idx / Kout, k = idx % Kout;
    dst[idx] = (k < Kin) ? src[(size_t)r * Kin + k] : 0.f;
}

__global__ void embed_k(const float* __restrict__ emb, const int* __restrict__ x,
                        float* __restrict__ y0) {
    int idx = blockIdx.x * blockDim.x + threadIdx.x;
    if (idx >= TSZ * BSZ * ESZ) return;
    int e   = idx % ESZ;
    int row = idx / ESZ;
    y0[idx] = emb[(size_t)x[row] * ESZ + e];
}

__global__ void wtrans_k(const float* __restrict__ W, float* __restrict__ Wt,
                         int Hp, int Gp) {
    __shared__ float tile[32][33];
    int jblk = blockIdx.x;
    int k0   = blockIdx.y * 32;
    for (int rr = 0; rr < 32; rr += 8) {
        int r = rr + threadIdx.y;
        int g = r >> 3, u = r & 7;
        int j = jblk * 8 + u;
        int orow = g * Hp + j;
        int k = k0 + threadIdx.x;
        tile[r][threadIdx.x] = (j < Hp && k < Hp) ? W[(size_t)orow * Hp + k] : 0.f;
    }
    __syncthreads();
    for (int kk = 0; kk < 32; kk += 8) {
        int k = k0 + kk + threadIdx.y;
        if (k < Hp)
            Wt[(size_t)k * Gp + jblk * 32 + threadIdx.x] = tile[threadIdx.x][kk + threadIdx.y];
    }
}

// ---------------- bf16x2-split tensor-core GEMM ----------------
// a = bf16_hi(a) + bf16_lo(a); D += Ah*Bh + Ah*Bl + Al*Bh via mma.m16n8k16.bf16.
__device__ __forceinline__ float tf32_rna(float x) {   // kept for lstm epilogue compat
    float r;
    asm("cvt.rna.tf32.f32 %0, %1;" : "=f"(r) : "f"(x));
    return r;
}

__device__ __forceinline__ void bfsplit2(float v0, float v1, uint32_t& h, uint32_t& l) {
    asm("cvt.rn.bf16x2.f32 %0, %1, %2;" : "=r"(h) : "f"(v1), "f"(v0));  // lo=v0, hi=v1
    float r0 = v0 - __uint_as_float(h << 16);
    float r1 = v1 - __uint_as_float(h & 0xffff0000u);
    asm("cvt.rn.bf16x2.f32 %0, %1, %2;" : "=r"(l) : "f"(r1), "f"(r0));
}

__device__ __forceinline__ void mma_bf16(float4& d, const uint32_t* a, const uint32_t* b) {
    asm volatile(
        "mma.sync.aligned.m16n8k16.row.col.f32.bf16.bf16.f32 "
        "{%0,%1,%2,%3}, {%4,%5,%6,%7}, {%8,%9}, {%0,%1,%2,%3};\n"
        : "+f"(d.x), "+f"(d.y), "+f"(d.z), "+f"(d.w)
        : "r"(a[0]), "r"(a[1]), "r"(a[2]), "r"(a[3]), "r"(b[0]), "r"(b[1]));
}

#define WSTR 12   // b32 words per 16-k row (8 data + 4 pad; 12*qr+qc covers all 32 banks)

// BM=BN=128, BK=16, 256 threads (8 warps 2m x 4n), warp tile 64x32.
// mode 0: C[m*N + n];  mode 1: C[((b*N + n)*T) + t], m = b*T + t (m-block = one b).
__global__ __launch_bounds__(256)
void gemm_tc(const float* __restrict__ A, const float* __restrict__ Bm,
             const float* __restrict__ bias1, const float* __restrict__ bias2,
             float* __restrict__ C, int M, int N, int K, int mode) {
    __shared__ uint32_t Ah[128 * WSTR];
    __shared__ uint32_t Al[128 * WSTR];
    __shared__ uint32_t Bh[128 * WSTR];
    __shared__ uint32_t Bl[128 * WSTR];

    const int tid  = threadIdx.x;
    const int lane = tid & 31;
    const int w    = tid >> 5;
    const int wm   = (w & 1) * 64;
    const int wn   = (w >> 1) * 32;
    const int qr   = lane >> 2;
    const int qc   = lane & 3;

    const int m0 = blockIdx.y * 128;
    const int n0 = blockIdx.x * 128;

    const int lrow = tid >> 1;
    const int lk   = (tid & 1) * 8;       // gmem k offset (floats)
    const int lw   = (tid & 1) * 4;       // smem word offset

    const float* Aptr = A + (size_t)(m0 + lrow) * K + lk;
    const float* Bptr = Bm + (size_t)(n0 + lrow) * K + lk;
    const bool bvalid = (n0 + lrow) < N;
    const int sbase = lrow * WSTR + lw;

    float4 acc[4][4];
#pragma unroll
    for (int i = 0; i < 4; i++)
#pragma unroll
        for (int j = 0; j < 4; j++) acc[i][j] = make_float4(0.f, 0.f, 0.f, 0.f);

    for (int k0 = 0; k0 < K; k0 += 16) {
        float4 av0 = *(const float4*)(Aptr + k0);
        float4 av1 = *(const float4*)(Aptr + k0 + 4);
        float4 bv0 = bvalid ? *(const float4*)(Bptr + k0) : make_float4(0.f, 0.f, 0.f, 0.f);
        float4 bv1 = bvalid ? *(const float4*)(Bptr + k0 + 4) : make_float4(0.f, 0.f, 0.f, 0.f);
        __syncthreads();   // previous compute done before smem overwrite
        {
            uint32_t h, l;
            bfsplit2(av0.x, av0.y, h, l); Ah[sbase + 0] = h; Al[sbase + 0] = l;
            bfsplit2(av0.z, av0.w, h, l); Ah[sbase + 1] = h; Al[sbase + 1] = l;
            bfsplit2(av1.x, av1.y, h, l); Ah[sbase + 2] = h; Al[sbase + 2] = l;
            bfsplit2(av1.z, av1.w, h, l); Ah[sbase + 3] = h; Al[sbase + 3] = l;
            bfsplit2(bv0.x, bv0.y, h, l); Bh[sbase + 0] = h; Bl[sbase + 0] = l;
            bfsplit2(bv0.z, bv0.w, h, l); Bh[sbase + 1] = h; Bl[sbase + 1] = l;
            bfsplit2(bv1.x, bv1.y, h, l); Bh[sbase + 2] = h; Bl[sbase + 2] = l;
            bfsplit2(bv1.z, bv1.w, h, l); Bh[sbase + 3] = h; Bl[sbase + 3] = l;
        }
        __syncthreads();

        // one m16n8k16 chunk covers the whole 16-k slab
        uint32_t a_h[4][4], a_l[4][4];
#pragma unroll
        for (int mt = 0; mt < 4; mt++) {
            int base = (wm + mt * 16 + qr) * WSTR + qc;
            a_h[mt][0] = Ah[base];
            a_h[mt][1] = Ah[base + 8 * WSTR];
            a_h[mt][2] = Ah[base + 4];
            a_h[mt][3] = Ah[base + 8 * WSTR + 4];
            a_l[mt][0] = Al[base];
            a_l[mt][1] = Al[base + 8 * WSTR];
            a_l[mt][2] = Al[base + 4];
            a_l[mt][3] = Al[base + 8 * WSTR + 4];
        }
#pragma unroll
        for (int nt = 0; nt < 4; nt++) {
            int nbase = (wn + nt * 8 + qr) * WSTR + qc;
            uint32_t b_h[2] = {Bh[nbase], Bh[nbase + 4]};
            uint32_t b_l[2] = {Bl[nbase], Bl[nbase + 4]};
#pragma unroll
            for (int mt = 0; mt < 4; mt++) {
                mma_bf16(acc[mt][nt], a_h[mt], b_h);
                mma_bf16(acc[mt][nt], a_h[mt], b_l);
                mma_bf16(acc[mt][nt], a_l[mt], b_h);
            }
        }
    }

#pragma unroll
    for (int mt = 0; mt < 4; mt++) {
        int mrow = m0 + wm + mt * 16 + qr;
#pragma unroll
        for (int nt = 0; nt < 4; nt++) {
            int n = n0 + wn + nt * 8 + 2 * qc;
            if (n >= N) continue;
            float b0 = 0.f, b1 = 0.f;
            if (bias1) { b0 += bias1[n]; b1 += bias1[n + 1]; }
            if (bias2) { b0 += bias2[n]; b1 += bias2[n + 1]; }
            float4 v = acc[mt][nt];
            if (mode == 0) {
                C[(size_t)mrow * N + n]           = v.x + b0;
                C[(size_t)mrow * N + n + 1]       = v.y + b1;
                C[(size_t)(mrow + 8) * N + n]     = v.z + b0;
                C[(size_t)(mrow + 8) * N + n + 1] = v.w + b1;
            } else {
                int bidx = m0 >> 7;
                int t = (mrow - m0);
                size_t base = ((size_t)bidx * N + n) * TSZ + t;
                C[base]           = v.x + b0;
                C[base + TSZ]     = v.y + b1;
                C[base + 8]       = v.z + b0;
                C[base + TSZ + 8] = v.w + b1;
            }
        }
    }
}

// ---------------- persistent LSTM layer kernel (unchanged from R14) ----------------
__device__ __forceinline__ float sigf(float z) { return 1.f / (1.f + expf(-z)); }

#define FMA2(d, a, b) \
    asm("fma.rn.f32x2 %0, %1, %2, %0;" : "+l"(d) : "l"(a), "l"(b))

__device__ __forceinline__ void grid_bar_flags(unsigned* flags, int nCTA, unsigned target) {
    __syncthreads();
    if (threadIdx.x == 0) {
        asm volatile("st.release.gpu.global.u32 [%0], %1;"
                     :: "l"(flags + (size_t)blockIdx.x * FLAGSTRIDE), "r"(target) : "memory");
    }
    if (threadIdx.x < nCTA) {
        unsigned v;
        do {
            asm volatile("ld.acquire.gpu.global.u32 %0, [%1];"
                         : "=r"(v) : "l"(flags + (size_t)threadIdx.x * FLAGSTRIDE) : "memory");
        } while ((int)(v - target) < 0);
    }
    __syncthreads();
}

__global__ __launch_bounds__(512, 1)
void lstm_layer_k(const float* __restrict__ pre, const float* __restrict__ Wt,
                  float* __restrict__ hA, float* __restrict__ hB,
                  float* __restrict__ cOut, float* __restrict__ y,
                  int Hp, int Gp, int ldy, unsigned* flags) {
    extern __shared__ float sm[];
    float* sW   = sm;
    float* red  = sm + Hp * 32;
    float* gsum = red + NSL * 32 * 16;
    float* cT   = gsum + 512;
    unsigned* sbase_p = (unsigned*)(cT + 128);

    const int tid  = threadIdx.x;
    const int jblk = blockIdx.x;
    const int nCTA = gridDim.x;
    const int lane = tid & 31;
    const int s    = tid >> 5;
    const int bg   = lane >> 3;
    const int cg   = lane & 7;
    const int G4 = 4 * Hp;

    const int p_out = tid >> 2;
    const int p_g   = tid & 3;
    const int p_eb  = p_out & 15;
    const int p_eu  = p_out >> 4;
    const int p_ej  = jblk * 8 + p_eu;
    const bool p_act = p_ej < Hp;
    const int p_ebg = p_eb >> 2, p_ebi = p_eb & 3;
    const int p_co  = p_g * 8 + p_eu;
    const int p_cg2 = p_co >> 2, p_c2 = p_co & 3;

    const int eb = tid & 15;
    const int eu = tid >> 4;
    const int ej = jblk * 8 + eu;
    const bool eact = (tid < 128) && (ej < Hp);
    const bool epad = (tid < 128) && (ej >= Hp) && (ej < ldy);

    if (tid == 0) *sbase_p = flags[(size_t)jblk * FLAGSTRIDE];
    for (int idx = tid; idx < Hp * 32; idx += 512) {
        int k = idx >> 5, rr = idx & 31;
        sW[idx] = Wt[(size_t)k * Gp + jblk * 32 + rr];
    }
    if (tid < 128) {
        cT[tid] = 0.f;
        if (ej < Hp) hA[ej * 16 + eb] = 0.f;
    }
    __syncthreads();
    const unsigned base = *sbase_p;

    float pg = 0.f;
    if (p_act)
        pg = __ldcg(pre + ((size_t)p_eb * TSZ + 0) * G4 + (size_t)p_g * Hp + p_ej);

    grid_bar_flags(flags, nCTA, base + 1u);

    const float4* sW4base = (const float4*)sW;

    for (int t = 0; t < TSZ; t++) {
        const float* hin = (t & 1) ? hB : hA;
        float* hout      = (t & 1) ? hA : hB;

        unsigned long long acc2[8];
#pragma unroll
        for (int i = 0; i < 8; i++) acc2[i] = 0ULL;

        const ulonglong2* hv = (const ulonglong2*)hin;
#pragma unroll 8
        for (int k = s; k < Hp; k += NSL) {
            float4 wq = sW4base[k * 8 + cg];
            ulonglong2 hp = hv[k * 4 + bg];
            unsigned long long w0, w1, w2, w3;
            asm("mov.b64 %0, {%1, %1};" : "=l"(w0) : "r"(__float_as_uint(wq.x)));
            asm("mov.b64 %0, {%1, %1};" : "=l"(w1) : "r"(__float_as_uint(wq.y)));
            asm("mov.b64 %0, {%1, %1};" : "=l"(w2) : "r"(__float_as_uint(wq.z)));
            asm("mov.b64 %0, {%1, %1};" : "=l"(w3) : "r"(__float_as_uint(wq.w)));
            FMA2(acc2[0], w0, hp.x); FMA2(acc2[1], w0, hp.y);
            FMA2(acc2[2], w1, hp.x); FMA2(acc2[3], w1, hp.y);
            FMA2(acc2[4], w2, hp.x); FMA2(acc2[5], w2, hp.y);
            FMA2(acc2[6], w3, hp.x); FMA2(acc2[7], w3, hp.y);
        }

        ulonglong2* rp = (ulonglong2*)&red[(s * 32 + lane) * 16];
        rp[0] = make_ulonglong2(acc2[0], acc2[1]);
        rp[1] = make_ulonglong2(acc2[2], acc2[3]);
        rp[2] = make_ulonglong2(acc2[4], acc2[5]);
        rp[3] = make_ulonglong2(acc2[6], acc2[7]);
        __syncthreads();

        {
            float sum = pg;
            int ridx = (p_ebg * 8 + p_cg2) * 16 + p_c2 * 4 + p_ebi;
#pragma unroll
            for (int s2 = 0; s2 < NSL; s2++)
                sum += red[s2 * 512 + ridx];
            gsum[tid] = sum;
        }
        __syncthreads();

        if (eact) {
            float4 gv = *(const float4*)&gsum[tid * 4];
            float ig = sigf(gv.x);
            float fg = sigf(gv.y);
            float gg = tanhf(gv.z);
            float og = sigf(gv.w);
            float c  = fg * cT[tid] + ig * gg;
            float hn = og * tanhf(c);
            cT[tid] = c;
            __stcg(&hout[ej * 16 + eb], hn);
            y[((size_t)eb * TSZ + t) * ldy + ej] = hn;
            if (t == TSZ - 1) cOut[ej * 16 + eb] = c;
        } else if (epad) {
            y[((size_t)eb * TSZ + t) * ldy + ej] = 0.f;
        }

        float pgn = 0.f;
        if (p_act && t + 1 < TSZ)
            pgn = __ldcg(pre + ((size_t)p_eb * TSZ + t + 1) * G4 + (size_t)p_g * Hp + p_ej);

        grid_bar_flags(flags, nCTA, base + (unsigned)(t + 2));
        pg = pgn;
    }
}

// ---------------- finalize ----------------
__global__ void finalize_k(const float* __restrict__ y1, const float* __restrict__ y2,
                           const float* __restrict__ y3, const float* __restrict__ cT1,
                           const float* __restrict__ cT2, const float* __restrict__ cT3,
                           float* __restrict__ out) {
    int i = blockIdx.x * blockDim.x + threadIdx.x;
    if (i >= 86400) return;
    const size_t O = (size_t)BSZ * VSZ * TSZ;
    if (i < 18400) {
        int b = i / 1150, j = i % 1150;
        out[O + i] = y1[((size_t)b * TSZ + 127) * HPAD + j];
    } else if (i < 36800) {
        int k = i - 18400; int b = k / 1150, j = k % 1150;
        out[O + i] = y2[((size_t)b * TSZ + 127) * HPAD + j];
    } else if (i < 43200) {
        int k = i - 36800; int b = k / 400, j = k % 400;
        out[O + i] = y3[((size_t)b * TSZ + 127) * 400 + j];
    } else if (i < 61600) {
        int k = i - 43200; int j = (k % 1150), b = k / 1150;
        out[O + i] = cT1[j * 16 + b];
    } else if (i < 80000) {
        int k = i - 61600; int j = (k % 1150), b = k / 1150;
        out[O + i] = cT2[j * 16 + b];
    } else {
        int k = i - 80000; int j = (k % 400), b = k / 400;
        out[O + i] = cT3[j * 16 + b];
    }
}

// ---------------- launch ----------------
extern "C" void kernel_launch(void* const* d_in, const int* in_sizes, int n_in,
                              void* d_out, int out_size) {
    const float* emb  = (const float*)d_in[0];
    const float* Wih1 = (const float*)d_in[1];
    const float* Whh1 = (const float*)d_in[2];
    const float* bih1 = (const float*)d_in[3];
    const float* bhh1 = (const float*)d_in[4];
    const float* Wih2 = (const float*)d_in[5];
    const float* Whh2 = (const float*)d_in[6];
    const float* bih2 = (const float*)d_in[7];
    const float* bhh2 = (const float*)d_in[8];
    const float* Wih3 = (const float*)d_in[9];
    const float* Whh3 = (const float*)d_in[10];
    const float* bih3 = (const float*)d_in[11];
    const float* bhh3 = (const float*)d_in[12];
    const float* linb = (const float*)d_in[13];
    const int*   x    = (const int*)d_in[14];
    float* out = (float*)d_out;

    float *y0, *y1, *y2, *y3, *pre, *Wt1, *Wt2, *Wt3, *W2p, *W3p;
    float *hTa, *hTb, *cT1, *cT2, *cT3;
    unsigned* flags;
    cudaGetSymbolAddress((void**)&y0,  g_y0);
    cudaGetSymbolAddress((void**)&y1,  g_y1);
    cudaGetSymbolAddress((void**)&y2,  g_y2);
    cudaGetSymbolAddress((void**)&y3,  g_y3);
    cudaGetSymbolAddress((void**)&pre, g_pre);
    cudaGetSymbolAddress((void**)&Wt1, g_Wt1);
    cudaGetSymbolAddress((void**)&Wt2, g_Wt2);
    cudaGetSymbolAddress((void**)&Wt3, g_Wt3);
    cudaGetSymbolAddress((void**)&W2p, g_Wih2p);
    cudaGetSymbolAddress((void**)&W3p, g_Wih3p);
    cudaGetSymbolAddress((void**)&hTa, g_hTa);
    cudaGetSymbolAddress((void**)&hTb, g_hTb);
    cudaGetSymbolAddress((void**)&cT1, g_cT1);
    cudaGetSymbolAddress((void**)&cT2, g_cT2);
    cudaGetSymbolAddress((void**)&cT3, g_cT3);
    cudaGetSymbolAddress((void**)&flags, g_flags);

    const int M = TSZ * BSZ;  // 2048
    const int SMEM12 = (HSZ * 32 + NSL * 32 * 16 + 512 + 128 + 32) * 4;
    const int SMEM3  = (ESZ * 32 + NSL * 32 * 16 + 512 + 128 + 32) * 4;
    static int smem_set = 0;
    if (!smem_set) {
        cudaFuncSetAttribute(lstm_layer_k, cudaFuncAttributeMaxDynamicSharedMemorySize, SMEM12);
        smem_set = 1;
    }

    // ----- layer 1: embed -> wtrans1 -> wtrans2 -> gemm1 (4th launch: profiled) -----
    embed_k<<<(TSZ * BSZ * ESZ + 255) / 256, 256>>>(emb, x, y0);
    wtrans_k<<<dim3(GP12 / 32, (HSZ + 31) / 32), dim3(32, 8)>>>(Whh1, Wt1, HSZ, GP12);
    wtrans_k<<<dim3(GP12 / 32, (HSZ + 31) / 32), dim3(32, 8)>>>(Whh2, Wt2, HSZ, GP12);
    gemm_tc<<<dim3((4 * HSZ + 127) / 128, M / 128), 256>>>(y0, Wih1, bih1, bhh1, pre,
                                                           M, 4 * HSZ, ESZ, 0);
    lstm_layer_k<<<GP12 / 32, 512, SMEM12>>>(pre, Wt1, hTa, hTb, cT1, y1,
                                             HSZ, GP12, HPAD, flags + 0 * 144 * FLAGSTRIDE);

    // ----- layer 2 -----
    pad_k<<<(4 * HSZ * HPAD + 255) / 256, 256>>>(Wih2, W2p, 4 * HSZ, HSZ, HPAD);
    gemm_tc<<<dim3((4 * HSZ + 127) / 128, M / 128), 256>>>(y1, W2p, bih2, bhh2, pre,
                                                           M, 4 * HSZ, HPAD, 0);
    lstm_layer_k<<<GP12 / 32, 512, SMEM12>>>(pre, Wt2, hTa, hTb, cT2, y2,
                                             HSZ, GP12, HPAD, flags + 1 * 144 * FLAGSTRIDE);

    // ----- layer 3 -----
    pad_k<<<(4 * ESZ * HPAD + 255) / 256, 256>>>(Wih3, W3p, 4 * ESZ, HSZ, HPAD);
    wtrans_k<<<dim3(GP3 / 32, (ESZ + 31) / 32), dim3(32, 8)>>>(Whh3, Wt3, ESZ, GP3);
    gemm_tc<<<dim3((4 * ESZ + 127) / 128, M / 128), 256>>>(y2, W3p, bih3, bhh3, pre,
                                                           M, 4 * ESZ, HPAD, 0);
    lstm_layer_k<<<GP3 / 32, 512, SMEM3>>>(pre, Wt3, hTa, hTb, cT3, y3,
                                           ESZ, GP3, ESZ, flags + 2 * 144 * FLAGSTRIDE);

    // ----- tied output projection into (B,V,T) -----
    gemm_tc<<<dim3(VSZ / 128, M / 128), 256>>>(y3, emb, linb, nullptr, out,
                                               M, VSZ, ESZ, 1);

    // ----- final states -----
    finalize_k<<<(86400 + 255) / 256, 256>>>(y1, y2, y3, cT1, cT2, cT3, out);
}

// round 16
// speedup vs baseline: 1.4650x; 1.0276x over previous
#include <cuda_runtime.h>
#include <stdint.h>
#include <math.h>

#define VSZ 32000
#define ESZ 400
#define HSZ 1150
#define HPAD 1152
#define BSZ 16
#define TSZ 128
#define GP12 4608
#define GP3  1600
#define FLAGSTRIDE 32
#define NSL 16

// ---------------- scratch ----------------
__device__ float g_y0[TSZ*BSZ*ESZ];
__device__ float g_y1[TSZ*BSZ*HPAD];
__device__ float g_y2[TSZ*BSZ*HPAD];
__device__ float g_y3[TSZ*BSZ*ESZ];
__device__ float g_pre[TSZ*BSZ*4*HSZ];
__device__ float g_Wt1[HSZ*GP12];
__device__ float g_Wt2[HSZ*GP12];
__device__ float g_Wt3[ESZ*GP3];
__device__ float g_Wih2p[4*HSZ*HPAD];
__device__ float g_Wih3p[4*ESZ*HPAD];
__device__ float g_hTa[HSZ*BSZ];
__device__ float g_hTb[HSZ*BSZ];
__device__ float g_cT1[HSZ*BSZ];
__device__ float g_cT2[HSZ*BSZ];
__device__ float g_cT3[ESZ*BSZ];
__device__ unsigned g_flags[3 * 144 * FLAGSTRIDE];

// ---------------- tiny utility kernels ----------------
__global__ void pad_k(const float* __restrict__ src, float* __restrict__ dst,
                      int rows, int Kin, int Kout) {
    int idx = blockIdx.x * blockDim.x + threadIdx.x;
    if (idx >= rows * Kout) return;
    int r = idx / Kout, k = idx % Kout;
    dst[idx] = (k < Kin) ? src[(size_t)r * Kin + k] : 0.f;
}

__global__ void embed_k(const float* __restrict__ emb, const int* __restrict__ x,
                        float* __restrict__ y0) {
    int idx = blockIdx.x * blockDim.x + threadIdx.x;
    if (idx >= TSZ * BSZ * ESZ) return;
    int e   = idx % ESZ;
    int row = idx / ESZ;
    y0[idx] = emb[(size_t)x[row] * ESZ + e];
}

__global__ void wtrans_k(const float* __restrict__ W, float* __restrict__ Wt,
                         int Hp, int Gp) {
    __shared__ float tile[32][33];
    int jblk = blockIdx.x;
    int k0   = blockIdx.y * 32;
    for (int rr = 0; rr < 32; rr += 8) {
        int r = rr + threadIdx.y;
        int g = r >> 3, u = r & 7;
        int j = jblk * 8 + u;
        int orow = g * Hp + j;
        int k = k0 + threadIdx.x;
        tile[r][threadIdx.x] = (j < Hp && k < Hp) ? W[(size_t)orow * Hp + k] : 0.f;
    }
    __syncthreads();
    for (int kk = 0; kk < 32; kk += 8) {
        int k = k0 + kk + threadIdx.y;
        if (k < Hp)
            Wt[(size_t)k * Gp + jblk * 32 + threadIdx.x] = tile[threadIdx.x][kk + threadIdx.y];
    }
}

// ---------------- bf16x2-split tensor-core GEMM (ldmatrix fragments) ----------------
__device__ __forceinline__ float tf32_rna(float x) {
    float r;
    asm("cvt.rna.tf32.f32 %0, %1;" : "=f"(r) : "f"(x));
    return r;
}

__device__ __forceinline__ void bfsplit2(float v0, float v1, uint32_t& h, uint32_t& l) {
    asm("cvt.rn.bf16x2.f32 %0, %1, %2;" : "=r"(h) : "f"(v1), "f"(v0));  // lo=v0, hi=v1
    float r0 = v0 - __uint_as_float(h << 16);
    float r1 = v1 - __uint_as_float(h & 0xffff0000u);
    asm("cvt.rn.bf16x2.f32 %0, %1, %2;" : "=r"(l) : "f"(r1), "f"(r0));
}

__device__ __forceinline__ void mma_bf16(float4& d, const uint32_t* a, const uint32_t* b) {
    asm volatile(
        "mma.sync.aligned.m16n8k16.row.col.f32.bf16.bf16.f32 "
        "{%0,%1,%2,%3}, {%4,%5,%6,%7}, {%8,%9}, {%0,%1,%2,%3};\n"
        : "+f"(d.x), "+f"(d.y), "+f"(d.z), "+f"(d.w)
        : "r"(a[0]), "r"(a[1]), "r"(a[2]), "r"(a[3]), "r"(b[0]), "r"(b[1]));
}

__device__ __forceinline__ void ldm_x4(uint32_t* r, uint32_t saddr) {
    asm volatile("ldmatrix.sync.aligned.m8n8.x4.shared.b16 {%0,%1,%2,%3}, [%4];"
                 : "=r"(r[0]), "=r"(r[1]), "=r"(r[2]), "=r"(r[3]) : "r"(saddr));
}

__device__ __forceinline__ void ldm_x2(uint32_t* r, uint32_t saddr) {
    asm volatile("ldmatrix.sync.aligned.m8n8.x2.shared.b16 {%0,%1}, [%2];"
                 : "=r"(r[0]), "=r"(r[1]) : "r"(saddr));
}

#define WSTR 12   // b32 words per 16-k row (8 data + 4 pad)

// BM=BN=128, BK=16, 256 threads (8 warps 2m x 4n), warp tile 64x32.
// mode 0: C[m*N + n];  mode 1: C[((b*N + n)*T) + t], m = b*T + t (m-block = one b).
__global__ __launch_bounds__(256)
void gemm_tc(const float* __restrict__ A, const float* __restrict__ Bm,
             const float* __restrict__ bias1, const float* __restrict__ bias2,
             float* __restrict__ C, int M, int N, int K, int mode) {
    __shared__ uint32_t Ah[128 * WSTR];
    __shared__ uint32_t Al[128 * WSTR];
    __shared__ uint32_t Bh[128 * WSTR];
    __shared__ uint32_t Bl[128 * WSTR];

    const int tid  = threadIdx.x;
    const int lane = tid & 31;
    const int w    = tid >> 5;
    const int wm   = (w & 1) * 64;
    const int wn   = (w >> 1) * 32;
    const int qr   = lane >> 2;
    const int qc   = lane & 3;

    const int m0 = blockIdx.y * 128;
    const int n0 = blockIdx.x * 128;

    const int lrow = tid >> 1;
    const int lk   = (tid & 1) * 8;       // gmem k offset (floats)
    const int lw   = (tid & 1) * 4;       // smem word offset

    const float* Aptr = A + (size_t)(m0 + lrow) * K + lk;
    const float* Bptr = Bm + (size_t)(n0 + lrow) * K + lk;
    const bool bvalid = (n0 + lrow) < N;
    const int sbase = lrow * WSTR + lw;

    // ldmatrix per-lane smem addresses (bytes)
    const uint32_t uAh = (uint32_t)__cvta_generic_to_shared(Ah);
    const uint32_t uAl = (uint32_t)__cvta_generic_to_shared(Al);
    const uint32_t uBh = (uint32_t)__cvta_generic_to_shared(Bh);
    const uint32_t uBl = (uint32_t)__cvta_generic_to_shared(Bl);
    const uint32_t aoff = ((uint32_t)((wm + (lane & 15)) * WSTR + ((lane >> 4) << 2))) * 4u;
    const uint32_t boff = ((uint32_t)((wn + (lane & 7)) * WSTR + (((lane >> 3) & 1) << 2))) * 4u;

    float4 acc[4][4];
#pragma unroll
    for (int i = 0; i < 4; i++)
#pragma unroll
        for (int j = 0; j < 4; j++) acc[i][j] = make_float4(0.f, 0.f, 0.f, 0.f);

    for (int k0 = 0; k0 < K; k0 += 16) {
        float4 av0 = *(const float4*)(Aptr + k0);
        float4 av1 = *(const float4*)(Aptr + k0 + 4);
        float4 bv0 = bvalid ? *(const float4*)(Bptr + k0) : make_float4(0.f, 0.f, 0.f, 0.f);
        float4 bv1 = bvalid ? *(const float4*)(Bptr + k0 + 4) : make_float4(0.f, 0.f, 0.f, 0.f);
        __syncthreads();
        {
            uint32_t h, l;
            bfsplit2(av0.x, av0.y, h, l); Ah[sbase + 0] = h; Al[sbase + 0] = l;
            bfsplit2(av0.z, av0.w, h, l); Ah[sbase + 1] = h; Al[sbase + 1] = l;
            bfsplit2(av1.x, av1.y, h, l); Ah[sbase + 2] = h; Al[sbase + 2] = l;
            bfsplit2(av1.z, av1.w, h, l); Ah[sbase + 3] = h; Al[sbase + 3] = l;
            bfsplit2(bv0.x, bv0.y, h, l); Bh[sbase + 0] = h; Bl[sbase + 0] = l;
            bfsplit2(bv0.z, bv0.w, h, l); Bh[sbase + 1] = h; Bl[sbase + 1] = l;
            bfsplit2(bv1.x, bv1.y, h, l); Bh[sbase + 2] = h; Bl[sbase + 2] = l;
            bfsplit2(bv1.z, bv1.w, h, l); Bh[sbase + 3] = h; Bl[sbase + 3] = l;
        }
        __syncthreads();

        uint32_t a_h[4][4], a_l[4][4];
#pragma unroll
        for (int mt = 0; mt < 4; mt++) {
            ldm_x4(a_h[mt], uAh + aoff + (uint32_t)(mt * 16 * WSTR * 4));
            ldm_x4(a_l[mt], uAl + aoff + (uint32_t)(mt * 16 * WSTR * 4));
        }
#pragma unroll
        for (int nt = 0; nt < 4; nt++) {
            uint32_t b_h[2], b_l[2];
            ldm_x2(b_h, uBh + boff + (uint32_t)(nt * 8 * WSTR * 4));
            ldm_x2(b_l, uBl + boff + (uint32_t)(nt * 8 * WSTR * 4));
#pragma unroll
            for (int mt = 0; mt < 4; mt++) {
                mma_bf16(acc[mt][nt], a_h[mt], b_h);
                mma_bf16(acc[mt][nt], a_h[mt], b_l);
                mma_bf16(acc[mt][nt], a_l[mt], b_h);
            }
        }
    }

#pragma unroll
    for (int mt = 0; mt < 4; mt++) {
        int mrow = m0 + wm + mt * 16 + qr;
#pragma unroll
        for (int nt = 0; nt < 4; nt++) {
            int n = n0 + wn + nt * 8 + 2 * qc;
            if (n >= N) continue;
            float b0 = 0.f, b1 = 0.f;
            if (bias1) { b0 += bias1[n]; b1 += bias1[n + 1]; }
            if (bias2) { b0 += bias2[n]; b1 += bias2[n + 1]; }
            float4 v = acc[mt][nt];
            if (mode == 0) {
                C[(size_t)mrow * N + n]           = v.x + b0;
                C[(size_t)mrow * N + n + 1]       = v.y + b1;
                C[(size_t)(mrow + 8) * N + n]     = v.z + b0;
                C[(size_t)(mrow + 8) * N + n + 1] = v.w + b1;
            } else {
                int bidx = m0 >> 7;
                int t = (mrow - m0);
                size_t base = ((size_t)bidx * N + n) * TSZ + t;
                C[base]           = v.x + b0;
                C[base + TSZ]     = v.y + b1;
                C[base + 8]       = v.z + b0;
                C[base + TSZ + 8] = v.w + b1;
            }
        }
    }
}

// ---------------- persistent LSTM layer kernel (unchanged from R15) ----------------
__device__ __forceinline__ float sigf(float z) { return 1.f / (1.f + expf(-z)); }

#define FMA2(d, a, b) \
    asm("fma.rn.f32x2 %0, %1, %2, %0;" : "+l"(d) : "l"(a), "l"(b))

__device__ __forceinline__ void grid_bar_flags(unsigned* flags, int nCTA, unsigned target) {
    __syncthreads();
    if (threadIdx.x == 0) {
        asm volatile("st.release.gpu.global.u32 [%0], %1;"
                     :: "l"(flags + (size_t)blockIdx.x * FLAGSTRIDE), "r"(target) : "memory");
    }
    if (threadIdx.x < nCTA) {
        unsigned v;
        do {
            asm volatile("ld.acquire.gpu.global.u32 %0, [%1];"
                         : "=r"(v) : "l"(flags + (size_t)threadIdx.x * FLAGSTRIDE) : "memory");
        } while ((int)(v - target) < 0);
    }
    __syncthreads();
}

__global__ __launch_bounds__(512, 1)
void lstm_layer_k(const float* __restrict__ pre, const float* __restrict__ Wt,
                  float* __restrict__ hA, float* __restrict__ hB,
                  float* __restrict__ cOut, float* __restrict__ y,
                  int Hp, int Gp, int ldy, unsigned* flags) {
    extern __shared__ float sm[];
    float* sW   = sm;
    float* red  = sm + Hp * 32;
    float* gsum = red + NSL * 32 * 16;
    float* cT   = gsum + 512;
    unsigned* sbase_p = (unsigned*)(cT + 128);

    const int tid  = threadIdx.x;
    const int jblk = blockIdx.x;
    const int nCTA = gridDim.x;
    const int lane = tid & 31;
    const int s    = tid >> 5;
    const int bg   = lane >> 3;
    const int cg   = lane & 7;
    const int G4 = 4 * Hp;

    const int p_out = tid >> 2;
    const int p_g   = tid & 3;
    const int p_eb  = p_out & 15;
    const int p_eu  = p_out >> 4;
    const int p_ej  = jblk * 8 + p_eu;
    const bool p_act = p_ej < Hp;
    const int p_ebg = p_eb >> 2, p_ebi = p_eb & 3;
    const int p_co  = p_g * 8 + p_eu;
    const int p_cg2 = p_co >> 2, p_c2 = p_co & 3;

    const int eb = tid & 15;
    const int eu = tid >> 4;
    const int ej = jblk * 8 + eu;
    const bool eact = (tid < 128) && (ej < Hp);
    const bool epad = (tid < 128) && (ej >= Hp) && (ej < ldy);

    if (tid == 0) *sbase_p = flags[(size_t)jblk * FLAGSTRIDE];
    for (int idx = tid; idx < Hp * 32; idx += 512) {
        int k = idx >> 5, rr = idx & 31;
        sW[idx] = Wt[(size_t)k * Gp + jblk * 32 + rr];
    }
    if (tid < 128) {
        cT[tid] = 0.f;
        if (ej < Hp) hA[ej * 16 + eb] = 0.f;
    }
    __syncthreads();
    const unsigned base = *sbase_p;

    float pg = 0.f;
    if (p_act)
        pg = __ldcg(pre + ((size_t)p_eb * TSZ + 0) * G4 + (size_t)p_g * Hp + p_ej);

    grid_bar_flags(flags, nCTA, base + 1u);

    const float4* sW4base = (const float4*)sW;

    for (int t = 0; t < TSZ; t++) {
        const float* hin = (t & 1) ? hB : hA;
        float* hout      = (t & 1) ? hA : hB;

        unsigned long long acc2[8];
#pragma unroll
        for (int i = 0; i < 8; i++) acc2[i] = 0ULL;

        const ulonglong2* hv = (const ulonglong2*)hin;
#pragma unroll 8
        for (int k = s; k < Hp; k += NSL) {
            float4 wq = sW4base[k * 8 + cg];
            ulonglong2 hp = hv[k * 4 + bg];
            unsigned long long w0, w1, w2, w3;
            asm("mov.b64 %0, {%1, %1};" : "=l"(w0) : "r"(__float_as_uint(wq.x)));
            asm("mov.b64 %0, {%1, %1};" : "=l"(w1) : "r"(__float_as_uint(wq.y)));
            asm("mov.b64 %0, {%1, %1};" : "=l"(w2) : "r"(__float_as_uint(wq.z)));
            asm("mov.b64 %0, {%1, %1};" : "=l"(w3) : "r"(__float_as_uint(wq.w)));
            FMA2(acc2[0], w0, hp.x); FMA2(acc2[1], w0, hp.y);
            FMA2(acc2[2], w1, hp.x); FMA2(acc2[3], w1, hp.y);
            FMA2(acc2[4], w2, hp.x); FMA2(acc2[5], w2, hp.y);
            FMA2(acc2[6], w3, hp.x); FMA2(acc2[7], w3, hp.y);
        }

        ulonglong2* rp = (ulonglong2*)&red[(s * 32 + lane) * 16];
        rp[0] = make_ulonglong2(acc2[0], acc2[1]);
        rp[1] = make_ulonglong2(acc2[2], acc2[3]);
        rp[2] = make_ulonglong2(acc2[4], acc2[5]);
        rp[3] = make_ulonglong2(acc2[6], acc2[7]);
        __syncthreads();

        {
            float sum = pg;
            int ridx = (p_ebg * 8 + p_cg2) * 16 + p_c2 * 4 + p_ebi;
#pragma unroll
            for (int s2 = 0; s2 < NSL; s2++)
                sum += red[s2 * 512 + ridx];
            gsum[tid] = sum;
        }
        __syncthreads();

        if (eact) {
            float4 gv = *(const float4*)&gsum[tid * 4];
            float ig = sigf(gv.x);
            float fg = sigf(gv.y);
            float gg = tanhf(gv.z);
            float og = sigf(gv.w);
            float c  = fg * cT[tid] + ig * gg;
            float hn = og * tanhf(c);
            cT[tid] = c;
            __stcg(&hout[ej * 16 + eb], hn);
            y[((size_t)eb * TSZ + t) * ldy + ej] = hn;
            if (t == TSZ - 1) cOut[ej * 16 + eb] = c;
        } else if (epad) {
            y[((size_t)eb * TSZ + t) * ldy + ej] = 0.f;
        }

        float pgn = 0.f;
        if (p_act && t + 1 < TSZ)
            pgn = __ldcg(pre + ((size_t)p_eb * TSZ + t + 1) * G4 + (size_t)p_g * Hp + p_ej);

        grid_bar_flags(flags, nCTA, base + (unsigned)(t + 2));
        pg = pgn;
    }
}

// ---------------- finalize ----------------
__global__ void finalize_k(const float* __restrict__ y1, const float* __restrict__ y2,
                           const float* __restrict__ y3, const float* __restrict__ cT1,
                           const float* __restrict__ cT2, const float* __restrict__ cT3,
                           float* __restrict__ out) {
    int i = blockIdx.x * blockDim.x + threadIdx.x;
    if (i >= 86400) return;
    const size_t O = (size_t)BSZ * VSZ * TSZ;
    if (i < 18400) {
        int b = i / 1150, j = i % 1150;
        out[O + i] = y1[((size_t)b * TSZ + 127) * HPAD + j];
    } else if (i < 36800) {
        int k = i - 18400; int b = k / 1150, j = k % 1150;
        out[O + i] = y2[((size_t)b * TSZ + 127) * HPAD + j];
    } else if (i < 43200) {
        int k = i - 36800; int b = k / 400, j = k % 400;
        out[O + i] = y3[((size_t)b * TSZ + 127) * 400 + j];
    } else if (i < 61600) {
        int k = i - 43200; int j = (k % 1150), b = k / 1150;
        out[O + i] = cT1[j * 16 + b];
    } else if (i < 80000) {
        int k = i - 61600; int j = (k % 1150), b = k / 1150;
        out[O + i] = cT2[j * 16 + b];
    } else {
        int k = i - 80000; int j = (k % 400), b = k / 400;
        out[O + i] = cT3[j * 16 + b];
    }
}

// ---------------- launch ----------------
extern "C" void kernel_launch(void* const* d_in, const int* in_sizes, int n_in,
                              void* d_out, int out_size) {
    const float* emb  = (const float*)d_in[0];
    const float* Wih1 = (const float*)d_in[1];
    const float* Whh1 = (const float*)d_in[2];
    const float* bih1 = (const float*)d_in[3];
    const float* bhh1 = (const float*)d_in[4];
    const float* Wih2 = (const float*)d_in[5];
    const float* Whh2 = (const float*)d_in[6];
    const float* bih2 = (const float*)d_in[7];
    const float* bhh2 = (const float*)d_in[8];
    const float* Wih3 = (const float*)d_in[9];
    const float* Whh3 = (const float*)d_in[10];
    const float* bih3 = (const float*)d_in[11];
    const float* bhh3 = (const float*)d_in[12];
    const float* linb = (const float*)d_in[13];
    const int*   x    = (const int*)d_in[14];
    float* out = (float*)d_out;

    float *y0, *y1, *y2, *y3, *pre, *Wt1, *Wt2, *Wt3, *W2p, *W3p;
    float *hTa, *hTb, *cT1, *cT2, *cT3;
    unsigned* flags;
    cudaGetSymbolAddress((void**)&y0,  g_y0);
    cudaGetSymbolAddress((void**)&y1,  g_y1);
    cudaGetSymbolAddress((void**)&y2,  g_y2);
    cudaGetSymbolAddress((void**)&y3,  g_y3);
    cudaGetSymbolAddress((void**)&pre, g_pre);
    cudaGetSymbolAddress((void**)&Wt1, g_Wt1);
    cudaGetSymbolAddress((void**)&Wt2, g_Wt2);
    cudaGetSymbolAddress((void**)&Wt3, g_Wt3);
    cudaGetSymbolAddress((void**)&W2p, g_Wih2p);
    cudaGetSymbolAddress((void**)&W3p, g_Wih3p);
    cudaGetSymbolAddress((void**)&hTa, g_hTa);
    cudaGetSymbolAddress((void**)&hTb, g_hTb);
    cudaGetSymbolAddress((void**)&cT1, g_cT1);
    cudaGetSymbolAddress((void**)&cT2, g_cT2);
    cudaGetSymbolAddress((void**)&cT3, g_cT3);
    cudaGetSymbolAddress((void**)&flags, g_flags);

    const int M = TSZ * BSZ;  // 2048
    const int SMEM12 = (HSZ * 32 + NSL * 32 * 16 + 512 + 128 + 32) * 4;
    const int SMEM3  = (ESZ * 32 + NSL * 32 * 16 + 512 + 128 + 32) * 4;
    static int smem_set = 0;
    if (!smem_set) {
        cudaFuncSetAttribute(lstm_layer_k, cudaFuncAttributeMaxDynamicSharedMemorySize, SMEM12);
        smem_set = 1;
    }

    // ----- layer 1: embed -> wtrans1 -> wtrans2 -> gemm1 (4th launch: profiled) -----
    embed_k<<<(TSZ * BSZ * ESZ + 255) / 256, 256>>>(emb, x, y0);
    wtrans_k<<<dim3(GP12 / 32, (HSZ + 31) / 32), dim3(32, 8)>>>(Whh1, Wt1, HSZ, GP12);
    wtrans_k<<<dim3(GP12 / 32, (HSZ + 31) / 32), dim3(32, 8)>>>(Whh2, Wt2, HSZ, GP12);
    gemm_tc<<<dim3((4 * HSZ + 127) / 128, M / 128), 256>>>(y0, Wih1, bih1, bhh1, pre,
                                                           M, 4 * HSZ, ESZ, 0);
    lstm_layer_k<<<GP12 / 32, 512, SMEM12>>>(pre, Wt1, hTa, hTb, cT1, y1,
                                             HSZ, GP12, HPAD, flags + 0 * 144 * FLAGSTRIDE);

    // ----- layer 2 -----
    pad_k<<<(4 * HSZ * HPAD + 255) / 256, 256>>>(Wih2, W2p, 4 * HSZ, HSZ, HPAD);
    gemm_tc<<<dim3((4 * HSZ + 127) / 128, M / 128), 256>>>(y1, W2p, bih2, bhh2, pre,
                                                           M, 4 * HSZ, HPAD, 0);
    lstm_layer_k<<<GP12 / 32, 512, SMEM12>>>(pre, Wt2, hTa, hTb, cT2, y2,
                                             HSZ, GP12, HPAD, flags + 1 * 144 * FLAGSTRIDE);

    // ----- layer 3 -----
    pad_k<<<(4 * ESZ * HPAD + 255) / 256, 256>>>(Wih3, W3p, 4 * ESZ, HSZ, HPAD);
    wtrans_k<<<dim3(GP3 / 32, (ESZ + 31) / 32), dim3(32, 8)>>>(Whh3, Wt3, ESZ, GP3);
    gemm_tc<<<dim3((4 * ESZ + 127) / 128, M / 128), 256>>>(y2, W3p, bih3, bhh3, pre,
                                                           M, 4 * ESZ, HPAD, 0);
    lstm_layer_k<<<GP3 / 32, 512, SMEM3>>>(pre, Wt3, hTa, hTb, cT3, y3,
                                           ESZ, GP3, ESZ, flags + 2 * 144 * FLAGSTRIDE);

    // ----- tied output projection into (B,V,T) -----
    gemm_tc<<<dim3(VSZ / 128, M / 128), 256>>>(y3, emb, linb, nullptr, out,
                                               M, VSZ, ESZ, 1);

    // ----- final states -----
    finalize_k<<<(86400 + 255) / 256, 256>>>(y1, y2, y3, cT1, cT2, cT3, out);
}